// round 14
// baseline (speedup 1.0000x reference)
#include <cuda_runtime.h>
#include <math.h>

// RotorQuantMSE — R14: R12 skeleton (dense float4/lane, shuffle boundary
// exchange, register matrices, one barrier per iteration, prefetch) widened
// to THREE interleaved row-streams per block. Numerics identical to R12.

#define D 768
#define NBLK 592    // 148 SMs * 4 (or *3 at higher regs — still >=1 block/SM wave)
#define NS 3

__device__ __forceinline__ void rotor_apply(
    float r0, float b1, float b2, float b3,
    float v1, float v2, float v3,
    float& o1, float& o2, float& o3)
{
    float t1 = fmaf(r0, v1, fmaf(b1, v2,  b2 * v3));
    float t2 = fmaf(r0, v2, fmaf(-b1, v1, b3 * v3));
    float t3 = fmaf(r0, v3, fmaf(-b2, v1, -b3 * v2));
    float t7 = fmaf(b1, v3, fmaf(-b2, v2,  b3 * v1));
    o1 = fmaf(r0, t1, fmaf( b1, t2, fmaf( b2, t3,  b3 * t7)));
    o2 = fmaf(r0, t2, fmaf(-b1, t1, fmaf( b3, t3, -b2 * t7)));
    o3 = fmaf(r0, t3, fmaf(-b2, t1, fmaf(-b3, t2,  b1 * t7)));
}

__device__ __forceinline__ void build_mat(const float* __restrict__ rp, float M[9])
{
    float r0 = __ldg(rp + 0);
    float4 bv = __ldg(reinterpret_cast<const float4*>(rp + 4));
    float b1 = bv.x, b2 = bv.y, b3 = bv.z;
    rotor_apply(r0, b1, b2, b3, 1.f, 0.f, 0.f, M[0], M[3], M[6]);
    rotor_apply(r0, b1, b2, b3, 0.f, 1.f, 0.f, M[1], M[4], M[7]);
    rotor_apply(r0, b1, b2, b3, 0.f, 0.f, 1.f, M[2], M[5], M[8]);
}

// argmin |y - c_k| over linspace(-1,1,16), ties -> lower index (R11/R12 path)
__device__ __forceinline__ float quantf(float y)
{
    float u = fmaf(y + 1.0f, 7.5f, -0.5f);
    return fminf(fmaxf(ceilf(u), 0.0f), 15.0f);
}

__device__ __forceinline__ void body(
    const float MA[9], const float MB[9], int m, int l,
    float4 a, float2 pv, float2 nx, float inv, float qs, float qb,
    float4& oh, float4& oi)
{
    float e0 = __shfl_up_sync(0xffffffffu, a.z, 1);
    float e1 = __shfl_up_sync(0xffffffffu, a.w, 1);
    float e6 = __shfl_down_sync(0xffffffffu, a.x, 1);
    float e7 = __shfl_down_sync(0xffffffffu, a.y, 1);
    if (l == 0)  { e0 = pv.x; e1 = pv.y; }
    if (l == 31) { e6 = nx.x; e7 = nx.y; }
    const float e2 = a.x, e3 = a.y, e4 = a.z, e5 = a.w;

    float vA0 = (m == 0) ? e2 : (m == 1) ? e1 : e0;
    float vA1 = (m == 0) ? e3 : (m == 1) ? e2 : e1;
    float vA2 = (m == 0) ? e4 : (m == 1) ? e3 : e2;
    float vB0 = (m == 0) ? e5 : (m == 1) ? e4 : e3;
    float vB1 = (m == 0) ? e6 : (m == 1) ? e5 : e4;
    float vB2 = (m == 0) ? e7 : (m == 1) ? e6 : e5;

    float yA0 = fmaf(MA[0], vA0, fmaf(MA[1], vA1, MA[2] * vA2)) * inv;
    float yA1 = fmaf(MA[3], vA0, fmaf(MA[4], vA1, MA[5] * vA2)) * inv;
    float yA2 = fmaf(MA[6], vA0, fmaf(MA[7], vA1, MA[8] * vA2)) * inv;
    float yB0 = fmaf(MB[0], vB0, fmaf(MB[1], vB1, MB[2] * vB2)) * inv;
    float yB1 = fmaf(MB[3], vB0, fmaf(MB[4], vB1, MB[5] * vB2)) * inv;
    float yB2 = fmaf(MB[6], vB0, fmaf(MB[7], vB1, MB[8] * vB2)) * inv;

    float fA0 = quantf(yA0), fA1 = quantf(yA1), fA2 = quantf(yA2);
    float fB0 = quantf(yB0), fB1 = quantf(yB1), fB2 = quantf(yB2);

    float qA0 = fmaf(fA0, qs, qb);
    float qA1 = fmaf(fA1, qs, qb);
    float qA2 = fmaf(fA2, qs, qb);
    float qB0 = fmaf(fB0, qs, qb);
    float qB1 = fmaf(fB1, qs, qb);
    float qB2 = fmaf(fB2, qs, qb);

    float hA0 = fmaf(MA[0], qA0, fmaf(MA[3], qA1, MA[6] * qA2));
    float hA1 = fmaf(MA[1], qA0, fmaf(MA[4], qA1, MA[7] * qA2));
    float hA2 = fmaf(MA[2], qA0, fmaf(MA[5], qA1, MA[8] * qA2));
    float hB0 = fmaf(MB[0], qB0, fmaf(MB[3], qB1, MB[6] * qB2));
    float hB1 = fmaf(MB[1], qB0, fmaf(MB[4], qB1, MB[7] * qB2));
    float hB2 = fmaf(MB[2], qB0, fmaf(MB[5], qB1, MB[8] * qB2));

    oh.x = (m == 0) ? hA0 : (m == 1) ? hA1 : hA2;
    oh.y = (m == 0) ? hA1 : (m == 1) ? hA2 : hB0;
    oh.z = (m == 0) ? hA2 : (m == 1) ? hB0 : hB1;
    oh.w = (m == 0) ? hB0 : (m == 1) ? hB1 : hB2;
    oi.x = (m == 0) ? fA0 : (m == 1) ? fA1 : fA2;
    oi.y = (m == 0) ? fA1 : (m == 1) ? fA2 : fB0;
    oi.z = (m == 0) ? fA2 : (m == 1) ? fB0 : fB1;
    oi.w = (m == 0) ? fB0 : (m == 1) ? fB1 : fB2;
}

__global__ void __launch_bounds__(192)
rotor_quant_kernel(const float* __restrict__ x,
                   const float* __restrict__ rotors,
                   float* __restrict__ xhat,
                   float* __restrict__ idx_out,
                   float* __restrict__ norms_out,
                   int N)
{
    const int w = threadIdx.x >> 5;
    const int l = threadIdx.x & 31;
    const int p0 = 128 * w + 4 * l;
    const int m  = p0 % 3;
    const int gA = p0 / 3;
    const int f4 = 32 * w + l;
    const int T3 = (N + 2) / 3;          // 2731 for N=8192

    float MA[9], MB[9];
    build_mat(rotors + (size_t)gA * 8, MA);
    build_mat(rotors + (size_t)(gA + 1) * 8, MB);

    const bool needPrev = (l == 0)  && ((128 * w) % 3 != 0);
    const bool needNext = (l == 31) && ((128 * (w + 1)) % 3 != 0);
    const float step = 2.0f / 15.0f;

    __shared__ __align__(16) float spart[2][NS][8];

    int r1 = blockIdx.x;                 // stream s handles row r1 + s*T3
    float4 a[NS]; float2 pv[NS], nx[NS];
    #pragma unroll
    for (int s = 0; s < NS; s++) {
        a[s] = make_float4(0, 0, 0, 0);
        pv[s] = make_float2(0, 0); nx[s] = make_float2(0, 0);
    }
    if (r1 < T3) {
        #pragma unroll
        for (int s = 0; s < NS; s++) {
            const int r = r1 + s * T3;
            if (r < N) {
                const float* xr = x + (size_t)r * D;
                a[s] = __ldg(reinterpret_cast<const float4*>(xr) + f4);
                if (needPrev) pv[s] = __ldg(reinterpret_cast<const float2*>(xr + 128 * w - 2));
                if (needNext) nx[s] = __ldg(reinterpret_cast<const float2*>(xr + 128 * (w + 1)));
            }
        }
    }

    int buf = 0;
    for (; r1 < T3; r1 += NBLK) {
        // norm partials, all streams, one barrier
        float sq[NS];
        #pragma unroll
        for (int s = 0; s < NS; s++)
            sq[s] = fmaf(a[s].x, a[s].x, fmaf(a[s].y, a[s].y,
                    fmaf(a[s].z, a[s].z, a[s].w * a[s].w)));
        #pragma unroll
        for (int o = 16; o; o >>= 1) {
            #pragma unroll
            for (int s = 0; s < NS; s++)
                sq[s] += __shfl_xor_sync(0xffffffffu, sq[s], o);
        }
        if (l == 0) {
            #pragma unroll
            for (int s = 0; s < NS; s++) spart[buf][s][w] = sq[s];
        }

        // prefetch next iteration's rows before the barrier
        const int n1 = r1 + NBLK;
        float4 a2[NS]; float2 pv2[NS], nx2[NS];
        #pragma unroll
        for (int s = 0; s < NS; s++) {
            a2[s] = make_float4(0, 0, 0, 0);
            pv2[s] = make_float2(0, 0); nx2[s] = make_float2(0, 0);
        }
        if (n1 < T3) {
            #pragma unroll
            for (int s = 0; s < NS; s++) {
                const int r = n1 + s * T3;
                if (r < N) {
                    const float* xr = x + (size_t)r * D;
                    a2[s] = __ldg(reinterpret_cast<const float4*>(xr) + f4);
                    if (needPrev) pv2[s] = __ldg(reinterpret_cast<const float2*>(xr + 128 * w - 2));
                    if (needNext) nx2[s] = __ldg(reinterpret_cast<const float2*>(xr + 128 * (w + 1)));
                }
            }
        }

        __syncthreads();
        float nrm[NS], invv[NS];
        #pragma unroll
        for (int s = 0; s < NS; s++) {
            float4 s4 = *reinterpret_cast<float4*>(spart[buf][s]);
            float2 s2 = *reinterpret_cast<float2*>(spart[buf][s] + 4);
            nrm[s] = fmaxf(sqrtf(s4.x + s4.y + s4.z + s4.w + s2.x + s2.y), 1e-8f);
            invv[s] = 1.0f / nrm[s];
        }
        buf ^= 1;

        #pragma unroll
        for (int s = 0; s < NS; s++) {
            const int r = r1 + s * T3;
            if (r < N) {
                float4 oh, oi;
                body(MA, MB, m, l, a[s], pv[s], nx[s],
                     invv[s], step * nrm[s], -nrm[s], oh, oi);
                reinterpret_cast<float4*>(xhat + (size_t)r * D)[f4] = oh;
                if (idx_out)
                    reinterpret_cast<float4*>(idx_out + (size_t)r * D)[f4] = oi;
                if (threadIdx.x == 0 && norms_out) norms_out[r] = nrm[s];
            }
        }

        #pragma unroll
        for (int s = 0; s < NS; s++) { a[s] = a2[s]; pv[s] = pv2[s]; nx[s] = nx2[s]; }
    }
}

extern "C" void kernel_launch(void* const* d_in, const int* in_sizes, int n_in,
                              void* d_out, int out_size)
{
    const float* x      = (const float*)d_in[0];   // [N, d]
    const float* rotors = (const float*)d_in[2];   // [G, 8]

    const int G = in_sizes[2] / 8;        // 256
    const int d = 3 * G;                  // 768
    const int N = in_sizes[0] / d;        // 8192

    float* out   = (float*)d_out;
    float* xhat  = out;
    float* idxp  = nullptr;
    float* normp = nullptr;
    const long nd = (long)N * d;
    if ((long)out_size >= 2 * nd)     idxp  = out + nd;
    if ((long)out_size >= 2 * nd + N) normp = out + 2 * nd;

    rotor_quant_kernel<<<NBLK, 192>>>(x, rotors, xhat, idxp, normp, N);
}

// round 15
// speedup vs baseline: 1.0965x; 1.0965x over previous
#include <cuda_runtime.h>
#include <math.h>

// RotorQuantMSE — R15: R12 (dual-row-stream, dense float4/lane, shuffle
// boundary exchange, register matrices, 1 barrier/iter, prefetch) with a
// mild register cap: __launch_bounds__(192, 5) -> 68 regs, 5 blocks/SM,
// grid = 740 (one wave). Numerics identical to R12.

#define D 768
#define NBLK 740    // 148 SMs * 5 blocks

__device__ __forceinline__ void rotor_apply(
    float r0, float b1, float b2, float b3,
    float v1, float v2, float v3,
    float& o1, float& o2, float& o3)
{
    float t1 = fmaf(r0, v1, fmaf(b1, v2,  b2 * v3));
    float t2 = fmaf(r0, v2, fmaf(-b1, v1, b3 * v3));
    float t3 = fmaf(r0, v3, fmaf(-b2, v1, -b3 * v2));
    float t7 = fmaf(b1, v3, fmaf(-b2, v2,  b3 * v1));
    o1 = fmaf(r0, t1, fmaf( b1, t2, fmaf( b2, t3,  b3 * t7)));
    o2 = fmaf(r0, t2, fmaf(-b1, t1, fmaf( b3, t3, -b2 * t7)));
    o3 = fmaf(r0, t3, fmaf(-b2, t1, fmaf(-b3, t2,  b1 * t7)));
}

__device__ __forceinline__ void build_mat(const float* __restrict__ rp, float M[9])
{
    float r0 = __ldg(rp + 0);
    float4 bv = __ldg(reinterpret_cast<const float4*>(rp + 4));
    float b1 = bv.x, b2 = bv.y, b3 = bv.z;
    rotor_apply(r0, b1, b2, b3, 1.f, 0.f, 0.f, M[0], M[3], M[6]);
    rotor_apply(r0, b1, b2, b3, 0.f, 1.f, 0.f, M[1], M[4], M[7]);
    rotor_apply(r0, b1, b2, b3, 0.f, 0.f, 1.f, M[2], M[5], M[8]);
}

// argmin |y - c_k| over linspace(-1,1,16), ties -> lower index
__device__ __forceinline__ float quantf(float y)
{
    float u = fmaf(y + 1.0f, 7.5f, -0.5f);
    return fminf(fmaxf(ceilf(u), 0.0f), 15.0f);
}

__device__ __forceinline__ void body(
    const float MA[9], const float MB[9], int m, int l,
    float4 a, float2 pv, float2 nx, float inv, float qs, float qb,
    float4& oh, float4& oi)
{
    float e0 = __shfl_up_sync(0xffffffffu, a.z, 1);
    float e1 = __shfl_up_sync(0xffffffffu, a.w, 1);
    float e6 = __shfl_down_sync(0xffffffffu, a.x, 1);
    float e7 = __shfl_down_sync(0xffffffffu, a.y, 1);
    if (l == 0)  { e0 = pv.x; e1 = pv.y; }
    if (l == 31) { e6 = nx.x; e7 = nx.y; }
    const float e2 = a.x, e3 = a.y, e4 = a.z, e5 = a.w;

    float vA0 = (m == 0) ? e2 : (m == 1) ? e1 : e0;
    float vA1 = (m == 0) ? e3 : (m == 1) ? e2 : e1;
    float vA2 = (m == 0) ? e4 : (m == 1) ? e3 : e2;
    float vB0 = (m == 0) ? e5 : (m == 1) ? e4 : e3;
    float vB1 = (m == 0) ? e6 : (m == 1) ? e5 : e4;
    float vB2 = (m == 0) ? e7 : (m == 1) ? e6 : e5;

    float yA0 = fmaf(MA[0], vA0, fmaf(MA[1], vA1, MA[2] * vA2)) * inv;
    float yA1 = fmaf(MA[3], vA0, fmaf(MA[4], vA1, MA[5] * vA2)) * inv;
    float yA2 = fmaf(MA[6], vA0, fmaf(MA[7], vA1, MA[8] * vA2)) * inv;
    float yB0 = fmaf(MB[0], vB0, fmaf(MB[1], vB1, MB[2] * vB2)) * inv;
    float yB1 = fmaf(MB[3], vB0, fmaf(MB[4], vB1, MB[5] * vB2)) * inv;
    float yB2 = fmaf(MB[6], vB0, fmaf(MB[7], vB1, MB[8] * vB2)) * inv;

    float fA0 = quantf(yA0), fA1 = quantf(yA1), fA2 = quantf(yA2);
    float fB0 = quantf(yB0), fB1 = quantf(yB1), fB2 = quantf(yB2);

    float qA0 = fmaf(fA0, qs, qb);
    float qA1 = fmaf(fA1, qs, qb);
    float qA2 = fmaf(fA2, qs, qb);
    float qB0 = fmaf(fB0, qs, qb);
    float qB1 = fmaf(fB1, qs, qb);
    float qB2 = fmaf(fB2, qs, qb);

    float hA0 = fmaf(MA[0], qA0, fmaf(MA[3], qA1, MA[6] * qA2));
    float hA1 = fmaf(MA[1], qA0, fmaf(MA[4], qA1, MA[7] * qA2));
    float hA2 = fmaf(MA[2], qA0, fmaf(MA[5], qA1, MA[8] * qA2));
    float hB0 = fmaf(MB[0], qB0, fmaf(MB[3], qB1, MB[6] * qB2));
    float hB1 = fmaf(MB[1], qB0, fmaf(MB[4], qB1, MB[7] * qB2));
    float hB2 = fmaf(MB[2], qB0, fmaf(MB[5], qB1, MB[8] * qB2));

    oh.x = (m == 0) ? hA0 : (m == 1) ? hA1 : hA2;
    oh.y = (m == 0) ? hA1 : (m == 1) ? hA2 : hB0;
    oh.z = (m == 0) ? hA2 : (m == 1) ? hB0 : hB1;
    oh.w = (m == 0) ? hB0 : (m == 1) ? hB1 : hB2;
    oi.x = (m == 0) ? fA0 : (m == 1) ? fA1 : fA2;
    oi.y = (m == 0) ? fA1 : (m == 1) ? fA2 : fB0;
    oi.z = (m == 0) ? fA2 : (m == 1) ? fB0 : fB1;
    oi.w = (m == 0) ? fB0 : (m == 1) ? fB1 : fB2;
}

__global__ void __launch_bounds__(192, 5)
rotor_quant_kernel(const float* __restrict__ x,
                   const float* __restrict__ rotors,
                   float* __restrict__ xhat,
                   float* __restrict__ idx_out,
                   float* __restrict__ norms_out,
                   int N)
{
    const int w = threadIdx.x >> 5;
    const int l = threadIdx.x & 31;
    const int p0 = 128 * w + 4 * l;
    const int m  = p0 % 3;
    const int gA = p0 / 3;
    const int f4 = 32 * w + l;
    const int HALF = N >> 1;

    float MA[9], MB[9];
    build_mat(rotors + (size_t)gA * 8, MA);
    build_mat(rotors + (size_t)(gA + 1) * 8, MB);

    const bool needPrev = (l == 0)  && ((128 * w) % 3 != 0);
    const bool needNext = (l == 31) && ((128 * (w + 1)) % 3 != 0);
    const float step = 2.0f / 15.0f;

    __shared__ __align__(16) float spart[2][2][8];

    int r1 = blockIdx.x;
    float4 aA = make_float4(0,0,0,0), aB = make_float4(0,0,0,0);
    float2 pvA = make_float2(0,0), nxA = make_float2(0,0);
    float2 pvB = make_float2(0,0), nxB = make_float2(0,0);
    if (r1 < HALF) {
        const float* xr = x + (size_t)r1 * D;
        aA = __ldg(reinterpret_cast<const float4*>(xr) + f4);
        if (needPrev) pvA = __ldg(reinterpret_cast<const float2*>(xr + 128 * w - 2));
        if (needNext) nxA = __ldg(reinterpret_cast<const float2*>(xr + 128 * (w + 1)));
        const float* xs = xr + (size_t)HALF * D;
        aB = __ldg(reinterpret_cast<const float4*>(xs) + f4);
        if (needPrev) pvB = __ldg(reinterpret_cast<const float2*>(xs + 128 * w - 2));
        if (needNext) nxB = __ldg(reinterpret_cast<const float2*>(xs + 128 * (w + 1)));
    }

    int buf = 0;
    for (; r1 < HALF; r1 += NBLK) {
        const int r2 = r1 + HALF;

        float s1 = fmaf(aA.x, aA.x, fmaf(aA.y, aA.y, fmaf(aA.z, aA.z, aA.w * aA.w)));
        float s2 = fmaf(aB.x, aB.x, fmaf(aB.y, aB.y, fmaf(aB.z, aB.z, aB.w * aB.w)));
        #pragma unroll
        for (int o = 16; o; o >>= 1) {
            s1 += __shfl_xor_sync(0xffffffffu, s1, o);
            s2 += __shfl_xor_sync(0xffffffffu, s2, o);
        }
        if (l == 0) { spart[buf][0][w] = s1; spart[buf][1][w] = s2; }

        const int n1 = r1 + NBLK;
        float4 aA2 = make_float4(0,0,0,0), aB2 = make_float4(0,0,0,0);
        float2 pvA2 = make_float2(0,0), nxA2 = make_float2(0,0);
        float2 pvB2 = make_float2(0,0), nxB2 = make_float2(0,0);
        if (n1 < HALF) {
            const float* xr = x + (size_t)n1 * D;
            aA2 = __ldg(reinterpret_cast<const float4*>(xr) + f4);
            if (needPrev) pvA2 = __ldg(reinterpret_cast<const float2*>(xr + 128 * w - 2));
            if (needNext) nxA2 = __ldg(reinterpret_cast<const float2*>(xr + 128 * (w + 1)));
            const float* xs = xr + (size_t)HALF * D;
            aB2 = __ldg(reinterpret_cast<const float4*>(xs) + f4);
            if (needPrev) pvB2 = __ldg(reinterpret_cast<const float2*>(xs + 128 * w - 2));
            if (needNext) nxB2 = __ldg(reinterpret_cast<const float2*>(xs + 128 * (w + 1)));
        }

        __syncthreads();
        float4 u4 = *reinterpret_cast<float4*>(spart[buf][0]);
        float2 u2 = *reinterpret_cast<float2*>(spart[buf][0] + 4);
        float4 v4 = *reinterpret_cast<float4*>(spart[buf][1]);
        float2 v2 = *reinterpret_cast<float2*>(spart[buf][1] + 4);
        buf ^= 1;
        const float nrm1 = fmaxf(sqrtf(u4.x + u4.y + u4.z + u4.w + u2.x + u2.y), 1e-8f);
        const float nrm2 = fmaxf(sqrtf(v4.x + v4.y + v4.z + v4.w + v2.x + v2.y), 1e-8f);
        const float inv1 = 1.0f / nrm1, inv2 = 1.0f / nrm2;

        float4 oh1, oi1, oh2, oi2;
        body(MA, MB, m, l, aA, pvA, nxA, inv1, step * nrm1, -nrm1, oh1, oi1);
        body(MA, MB, m, l, aB, pvB, nxB, inv2, step * nrm2, -nrm2, oh2, oi2);

        reinterpret_cast<float4*>(xhat + (size_t)r1 * D)[f4] = oh1;
        reinterpret_cast<float4*>(xhat + (size_t)r2 * D)[f4] = oh2;
        if (idx_out) {
            reinterpret_cast<float4*>(idx_out + (size_t)r1 * D)[f4] = oi1;
            reinterpret_cast<float4*>(idx_out + (size_t)r2 * D)[f4] = oi2;
        }
        if (threadIdx.x == 0 && norms_out) {
            norms_out[r1] = nrm1;
            norms_out[r2] = nrm2;
        }

        aA = aA2; pvA = pvA2; nxA = nxA2;
        aB = aB2; pvB = pvB2; nxB = nxB2;
    }
}

extern "C" void kernel_launch(void* const* d_in, const int* in_sizes, int n_in,
                              void* d_out, int out_size)
{
    const float* x      = (const float*)d_in[0];   // [N, d]
    const float* rotors = (const float*)d_in[2];   // [G, 8]

    const int G = in_sizes[2] / 8;        // 256
    const int d = 3 * G;                  // 768
    const int N = in_sizes[0] / d;        // 8192

    float* out   = (float*)d_out;
    float* xhat  = out;
    float* idxp  = nullptr;
    float* normp = nullptr;
    const long nd = (long)N * d;
    if ((long)out_size >= 2 * nd)     idxp  = out + nd;
    if ((long)out_size >= 2 * nd + N) normp = out + 2 * nd;

    rotor_quant_kernel<<<NBLK, 192>>>(x, rotors, xhat, idxp, normp, N);
}

// round 16
// speedup vs baseline: 1.1342x; 1.0343x over previous
#include <cuda_runtime.h>
#include <math.h>

// RotorQuantMSE — FINAL (= R12, measured best 18.94 us): dual-row-stream
// persistent kernel. Block (192 thr = 6 warps) processes rows r and r+N/2 per
// iteration: dense float4/lane global access, 4-shuffle boundary exchange
// (a float4 spans exactly 2 groups of 3), per-thread rotation matrices from
// the rotor sandwich held in registers (inverse = transpose), one barrier per
// iteration for both rows' norm partials, prefetch-before-barrier, float-domain
// quantization, nrm folded into dequant.

#define D 768
#define NBLK 592    // 148 SMs * 4 — single wave at natural 80 regs

__device__ __forceinline__ void rotor_apply(
    float r0, float b1, float b2, float b3,
    float v1, float v2, float v3,
    float& o1, float& o2, float& o3)
{
    float t1 = fmaf(r0, v1, fmaf(b1, v2,  b2 * v3));
    float t2 = fmaf(r0, v2, fmaf(-b1, v1, b3 * v3));
    float t3 = fmaf(r0, v3, fmaf(-b2, v1, -b3 * v2));
    float t7 = fmaf(b1, v3, fmaf(-b2, v2,  b3 * v1));
    o1 = fmaf(r0, t1, fmaf( b1, t2, fmaf( b2, t3,  b3 * t7)));
    o2 = fmaf(r0, t2, fmaf(-b1, t1, fmaf( b3, t3, -b2 * t7)));
    o3 = fmaf(r0, t3, fmaf(-b2, t1, fmaf(-b3, t2,  b1 * t7)));
}

__device__ __forceinline__ void build_mat(const float* __restrict__ rp, float M[9])
{
    float r0 = __ldg(rp + 0);
    float4 bv = __ldg(reinterpret_cast<const float4*>(rp + 4));
    float b1 = bv.x, b2 = bv.y, b3 = bv.z;
    rotor_apply(r0, b1, b2, b3, 1.f, 0.f, 0.f, M[0], M[3], M[6]);
    rotor_apply(r0, b1, b2, b3, 0.f, 1.f, 0.f, M[1], M[4], M[7]);
    rotor_apply(r0, b1, b2, b3, 0.f, 0.f, 1.f, M[2], M[5], M[8]);
}

// float-domain quant, numerically identical to (int)ceilf + int clamp:
// argmin |y - c_k| over linspace(-1,1,16), ties -> lower index.
__device__ __forceinline__ float quantf(float y)
{
    float u = fmaf(y + 1.0f, 7.5f, -0.5f);
    return fminf(fmaxf(ceilf(u), 0.0f), 15.0f);
}

// One row-stream's work. qs = step*nrm, qb = -nrm (dequant pre-scaled by nrm).
__device__ __forceinline__ void body(
    const float MA[9], const float MB[9], int m, int l,
    float4 a, float2 pv, float2 nx, float inv, float qs, float qb,
    float4& oh, float4& oi)
{
    float e0 = __shfl_up_sync(0xffffffffu, a.z, 1);
    float e1 = __shfl_up_sync(0xffffffffu, a.w, 1);
    float e6 = __shfl_down_sync(0xffffffffu, a.x, 1);
    float e7 = __shfl_down_sync(0xffffffffu, a.y, 1);
    if (l == 0)  { e0 = pv.x; e1 = pv.y; }
    if (l == 31) { e6 = nx.x; e7 = nx.y; }
    const float e2 = a.x, e3 = a.y, e4 = a.z, e5 = a.w;

    float vA0 = (m == 0) ? e2 : (m == 1) ? e1 : e0;
    float vA1 = (m == 0) ? e3 : (m == 1) ? e2 : e1;
    float vA2 = (m == 0) ? e4 : (m == 1) ? e3 : e2;
    float vB0 = (m == 0) ? e5 : (m == 1) ? e4 : e3;
    float vB1 = (m == 0) ? e6 : (m == 1) ? e5 : e4;
    float vB2 = (m == 0) ? e7 : (m == 1) ? e6 : e5;

    float yA0 = fmaf(MA[0], vA0, fmaf(MA[1], vA1, MA[2] * vA2)) * inv;
    float yA1 = fmaf(MA[3], vA0, fmaf(MA[4], vA1, MA[5] * vA2)) * inv;
    float yA2 = fmaf(MA[6], vA0, fmaf(MA[7], vA1, MA[8] * vA2)) * inv;
    float yB0 = fmaf(MB[0], vB0, fmaf(MB[1], vB1, MB[2] * vB2)) * inv;
    float yB1 = fmaf(MB[3], vB0, fmaf(MB[4], vB1, MB[5] * vB2)) * inv;
    float yB2 = fmaf(MB[6], vB0, fmaf(MB[7], vB1, MB[8] * vB2)) * inv;

    float fA0 = quantf(yA0), fA1 = quantf(yA1), fA2 = quantf(yA2);
    float fB0 = quantf(yB0), fB1 = quantf(yB1), fB2 = quantf(yB2);

    // dequant pre-scaled by nrm
    float qA0 = fmaf(fA0, qs, qb);
    float qA1 = fmaf(fA1, qs, qb);
    float qA2 = fmaf(fA2, qs, qb);
    float qB0 = fmaf(fB0, qs, qb);
    float qB1 = fmaf(fB1, qs, qb);
    float qB2 = fmaf(fB2, qs, qb);

    // inverse rotation = M^T (result already scaled by nrm)
    float hA0 = fmaf(MA[0], qA0, fmaf(MA[3], qA1, MA[6] * qA2));
    float hA1 = fmaf(MA[1], qA0, fmaf(MA[4], qA1, MA[7] * qA2));
    float hA2 = fmaf(MA[2], qA0, fmaf(MA[5], qA1, MA[8] * qA2));
    float hB0 = fmaf(MB[0], qB0, fmaf(MB[3], qB1, MB[6] * qB2));
    float hB1 = fmaf(MB[1], qB0, fmaf(MB[4], qB1, MB[7] * qB2));
    float hB2 = fmaf(MB[2], qB0, fmaf(MB[5], qB1, MB[8] * qB2));

    oh.x = (m == 0) ? hA0 : (m == 1) ? hA1 : hA2;
    oh.y = (m == 0) ? hA1 : (m == 1) ? hA2 : hB0;
    oh.z = (m == 0) ? hA2 : (m == 1) ? hB0 : hB1;
    oh.w = (m == 0) ? hB0 : (m == 1) ? hB1 : hB2;
    oi.x = (m == 0) ? fA0 : (m == 1) ? fA1 : fA2;
    oi.y = (m == 0) ? fA1 : (m == 1) ? fA2 : fB0;
    oi.z = (m == 0) ? fA2 : (m == 1) ? fB0 : fB1;
    oi.w = (m == 0) ? fB0 : (m == 1) ? fB1 : fB2;
}

__global__ void __launch_bounds__(192)
rotor_quant_kernel(const float* __restrict__ x,
                   const float* __restrict__ rotors,
                   float* __restrict__ xhat,
                   float* __restrict__ idx_out,
                   float* __restrict__ norms_out,
                   int N)
{
    const int w = threadIdx.x >> 5;      // warp 0..5
    const int l = threadIdx.x & 31;
    const int p0 = 128 * w + 4 * l;
    const int m  = p0 % 3;
    const int gA = p0 / 3;
    const int f4 = 32 * w + l;
    const int HALF = N >> 1;             // 4096

    float MA[9], MB[9];
    build_mat(rotors + (size_t)gA * 8, MA);
    build_mat(rotors + (size_t)(gA + 1) * 8, MB);

    const bool needPrev = (l == 0)  && ((128 * w) % 3 != 0);
    const bool needNext = (l == 31) && ((128 * (w + 1)) % 3 != 0);
    const float step = 2.0f / 15.0f;

    __shared__ __align__(16) float spart[2][2][8];   // [buf][stream][warp]

    // prologue loads for both streams' first rows
    int r1 = blockIdx.x;                 // stream 0: rows [0, HALF)
    float4 aA = make_float4(0, 0, 0, 0), aB = make_float4(0, 0, 0, 0);
    float2 pvA = make_float2(0, 0), nxA = make_float2(0, 0);
    float2 pvB = make_float2(0, 0), nxB = make_float2(0, 0);
    if (r1 < HALF) {
        const float* xr = x + (size_t)r1 * D;
        aA = __ldg(reinterpret_cast<const float4*>(xr) + f4);
        if (needPrev) pvA = __ldg(reinterpret_cast<const float2*>(xr + 128 * w - 2));
        if (needNext) nxA = __ldg(reinterpret_cast<const float2*>(xr + 128 * (w + 1)));
        const float* xs = xr + (size_t)HALF * D;
        aB = __ldg(reinterpret_cast<const float4*>(xs) + f4);
        if (needPrev) pvB = __ldg(reinterpret_cast<const float2*>(xs + 128 * w - 2));
        if (needNext) nxB = __ldg(reinterpret_cast<const float2*>(xs + 128 * (w + 1)));
    }

    int buf = 0;
    for (; r1 < HALF; r1 += NBLK) {
        const int r2 = r1 + HALF;

        // norm partials for both streams, one barrier
        float s1 = fmaf(aA.x, aA.x, fmaf(aA.y, aA.y, fmaf(aA.z, aA.z, aA.w * aA.w)));
        float s2 = fmaf(aB.x, aB.x, fmaf(aB.y, aB.y, fmaf(aB.z, aB.z, aB.w * aB.w)));
        #pragma unroll
        for (int o = 16; o; o >>= 1) {
            s1 += __shfl_xor_sync(0xffffffffu, s1, o);
            s2 += __shfl_xor_sync(0xffffffffu, s2, o);
        }
        if (l == 0) { spart[buf][0][w] = s1; spart[buf][1][w] = s2; }

        // prefetch next rows before the barrier
        const int n1 = r1 + NBLK;
        float4 aA2 = make_float4(0, 0, 0, 0), aB2 = make_float4(0, 0, 0, 0);
        float2 pvA2 = make_float2(0, 0), nxA2 = make_float2(0, 0);
        float2 pvB2 = make_float2(0, 0), nxB2 = make_float2(0, 0);
        if (n1 < HALF) {
            const float* xr = x + (size_t)n1 * D;
            aA2 = __ldg(reinterpret_cast<const float4*>(xr) + f4);
            if (needPrev) pvA2 = __ldg(reinterpret_cast<const float2*>(xr + 128 * w - 2));
            if (needNext) nxA2 = __ldg(reinterpret_cast<const float2*>(xr + 128 * (w + 1)));
            const float* xs = xr + (size_t)HALF * D;
            aB2 = __ldg(reinterpret_cast<const float4*>(xs) + f4);
            if (needPrev) pvB2 = __ldg(reinterpret_cast<const float2*>(xs + 128 * w - 2));
            if (needNext) nxB2 = __ldg(reinterpret_cast<const float2*>(xs + 128 * (w + 1)));
        }

        __syncthreads();
        float4 u4 = *reinterpret_cast<float4*>(spart[buf][0]);
        float2 u2 = *reinterpret_cast<float2*>(spart[buf][0] + 4);
        float4 v4 = *reinterpret_cast<float4*>(spart[buf][1]);
        float2 v2 = *reinterpret_cast<float2*>(spart[buf][1] + 4);
        buf ^= 1;
        const float nrm1 = fmaxf(sqrtf(u4.x + u4.y + u4.z + u4.w + u2.x + u2.y), 1e-8f);
        const float nrm2 = fmaxf(sqrtf(v4.x + v4.y + v4.z + v4.w + v2.x + v2.y), 1e-8f);
        const float inv1 = 1.0f / nrm1, inv2 = 1.0f / nrm2;
        const float qs1 = step * nrm1, qb1 = -nrm1;
        const float qs2 = step * nrm2, qb2 = -nrm2;

        float4 oh1, oi1, oh2, oi2;
        body(MA, MB, m, l, aA, pvA, nxA, inv1, qs1, qb1, oh1, oi1);
        body(MA, MB, m, l, aB, pvB, nxB, inv2, qs2, qb2, oh2, oi2);

        reinterpret_cast<float4*>(xhat + (size_t)r1 * D)[f4] = oh1;
        reinterpret_cast<float4*>(xhat + (size_t)r2 * D)[f4] = oh2;
        if (idx_out) {
            reinterpret_cast<float4*>(idx_out + (size_t)r1 * D)[f4] = oi1;
            reinterpret_cast<float4*>(idx_out + (size_t)r2 * D)[f4] = oi2;
        }
        if (threadIdx.x == 0 && norms_out) {
            norms_out[r1] = nrm1;
            norms_out[r2] = nrm2;
        }

        aA = aA2; pvA = pvA2; nxA = nxA2;
        aB = aB2; pvB = pvB2; nxB = nxB2;
    }
}

extern "C" void kernel_launch(void* const* d_in, const int* in_sizes, int n_in,
                              void* d_out, int out_size)
{
    const float* x      = (const float*)d_in[0];   // [N, d]
    const float* rotors = (const float*)d_in[2];   // [G, 8]

    const int G = in_sizes[2] / 8;        // 256
    const int d = 3 * G;                  // 768
    const int N = in_sizes[0] / d;        // 8192

    float* out   = (float*)d_out;
    float* xhat  = out;
    float* idxp  = nullptr;
    float* normp = nullptr;
    const long nd = (long)N * d;
    if ((long)out_size >= 2 * nd)     idxp  = out + nd;
    if ((long)out_size >= 2 * nd + N) normp = out + 2 * nd;

    rotor_quant_kernel<<<NBLK, 192>>>(x, rotors, xhat, idxp, normp, N);
}

// round 17
// speedup vs baseline: 1.2301x; 1.0846x over previous
#include <cuda_runtime.h>
#include <math.h>

// RotorQuantMSE — R17: R12/R16 (measured best) with the provably-dead
// quantizer clamps removed. y is a rotated unit-vector component => |y|<=1+eps
// => u=(y+1)*7.5-0.5 in [-0.5-eps, 14.5+eps] => ceilf(u) already lands in
// [-0, 15]; the fminf/fmaxf pair (24 ALU ops/iter) can never fire.
// Quant rounding sequence (FADD; FFMA; CEIL) unchanged from R12.

#define D 768
#define NBLK 592    // 148 SMs * 4 — single wave at natural 80 regs

__device__ __forceinline__ void rotor_apply(
    float r0, float b1, float b2, float b3,
    float v1, float v2, float v3,
    float& o1, float& o2, float& o3)
{
    float t1 = fmaf(r0, v1, fmaf(b1, v2,  b2 * v3));
    float t2 = fmaf(r0, v2, fmaf(-b1, v1, b3 * v3));
    float t3 = fmaf(r0, v3, fmaf(-b2, v1, -b3 * v2));
    float t7 = fmaf(b1, v3, fmaf(-b2, v2,  b3 * v1));
    o1 = fmaf(r0, t1, fmaf( b1, t2, fmaf( b2, t3,  b3 * t7)));
    o2 = fmaf(r0, t2, fmaf(-b1, t1, fmaf( b3, t3, -b2 * t7)));
    o3 = fmaf(r0, t3, fmaf(-b2, t1, fmaf(-b3, t2,  b1 * t7)));
}

__device__ __forceinline__ void build_mat(const float* __restrict__ rp, float M[9])
{
    float r0 = __ldg(rp + 0);
    float4 bv = __ldg(reinterpret_cast<const float4*>(rp + 4));
    float b1 = bv.x, b2 = bv.y, b3 = bv.z;
    rotor_apply(r0, b1, b2, b3, 1.f, 0.f, 0.f, M[0], M[3], M[6]);
    rotor_apply(r0, b1, b2, b3, 0.f, 1.f, 0.f, M[1], M[4], M[7]);
    rotor_apply(r0, b1, b2, b3, 0.f, 0.f, 1.f, M[2], M[5], M[8]);
}

// argmin |y - c_k| over linspace(-1,1,16), ties -> lower index.
// No clamp: u in [-0.5-eps, 14.5+eps] by construction (see header comment).
__device__ __forceinline__ float quantf(float y)
{
    return ceilf(fmaf(y + 1.0f, 7.5f, -0.5f));
}

// One row-stream's work. qs = step*nrm, qb = -nrm (dequant pre-scaled by nrm).
__device__ __forceinline__ void body(
    const float MA[9], const float MB[9], int m, int l,
    float4 a, float2 pv, float2 nx, float inv, float qs, float qb,
    float4& oh, float4& oi)
{
    float e0 = __shfl_up_sync(0xffffffffu, a.z, 1);
    float e1 = __shfl_up_sync(0xffffffffu, a.w, 1);
    float e6 = __shfl_down_sync(0xffffffffu, a.x, 1);
    float e7 = __shfl_down_sync(0xffffffffu, a.y, 1);
    if (l == 0)  { e0 = pv.x; e1 = pv.y; }
    if (l == 31) { e6 = nx.x; e7 = nx.y; }
    const float e2 = a.x, e3 = a.y, e4 = a.z, e5 = a.w;

    float vA0 = (m == 0) ? e2 : (m == 1) ? e1 : e0;
    float vA1 = (m == 0) ? e3 : (m == 1) ? e2 : e1;
    float vA2 = (m == 0) ? e4 : (m == 1) ? e3 : e2;
    float vB0 = (m == 0) ? e5 : (m == 1) ? e4 : e3;
    float vB1 = (m == 0) ? e6 : (m == 1) ? e5 : e4;
    float vB2 = (m == 0) ? e7 : (m == 1) ? e6 : e5;

    float yA0 = fmaf(MA[0], vA0, fmaf(MA[1], vA1, MA[2] * vA2)) * inv;
    float yA1 = fmaf(MA[3], vA0, fmaf(MA[4], vA1, MA[5] * vA2)) * inv;
    float yA2 = fmaf(MA[6], vA0, fmaf(MA[7], vA1, MA[8] * vA2)) * inv;
    float yB0 = fmaf(MB[0], vB0, fmaf(MB[1], vB1, MB[2] * vB2)) * inv;
    float yB1 = fmaf(MB[3], vB0, fmaf(MB[4], vB1, MB[5] * vB2)) * inv;
    float yB2 = fmaf(MB[6], vB0, fmaf(MB[7], vB1, MB[8] * vB2)) * inv;

    float fA0 = quantf(yA0), fA1 = quantf(yA1), fA2 = quantf(yA2);
    float fB0 = quantf(yB0), fB1 = quantf(yB1), fB2 = quantf(yB2);

    // dequant pre-scaled by nrm
    float qA0 = fmaf(fA0, qs, qb);
    float qA1 = fmaf(fA1, qs, qb);
    float qA2 = fmaf(fA2, qs, qb);
    float qB0 = fmaf(fB0, qs, qb);
    float qB1 = fmaf(fB1, qs, qb);
    float qB2 = fmaf(fB2, qs, qb);

    // inverse rotation = M^T (result already scaled by nrm)
    float hA0 = fmaf(MA[0], qA0, fmaf(MA[3], qA1, MA[6] * qA2));
    float hA1 = fmaf(MA[1], qA0, fmaf(MA[4], qA1, MA[7] * qA2));
    float hA2 = fmaf(MA[2], qA0, fmaf(MA[5], qA1, MA[8] * qA2));
    float hB0 = fmaf(MB[0], qB0, fmaf(MB[3], qB1, MB[6] * qB2));
    float hB1 = fmaf(MB[1], qB0, fmaf(MB[4], qB1, MB[7] * qB2));
    float hB2 = fmaf(MB[2], qB0, fmaf(MB[5], qB1, MB[8] * qB2));

    oh.x = (m == 0) ? hA0 : (m == 1) ? hA1 : hA2;
    oh.y = (m == 0) ? hA1 : (m == 1) ? hA2 : hB0;
    oh.z = (m == 0) ? hA2 : (m == 1) ? hB0 : hB1;
    oh.w = (m == 0) ? hB0 : (m == 1) ? hB1 : hB2;
    oi.x = (m == 0) ? fA0 : (m == 1) ? fA1 : fA2;
    oi.y = (m == 0) ? fA1 : (m == 1) ? fA2 : fB0;
    oi.z = (m == 0) ? fA2 : (m == 1) ? fB0 : fB1;
    oi.w = (m == 0) ? fB0 : (m == 1) ? fB1 : fB2;
}

__global__ void __launch_bounds__(192)
rotor_quant_kernel(const float* __restrict__ x,
                   const float* __restrict__ rotors,
                   float* __restrict__ xhat,
                   float* __restrict__ idx_out,
                   float* __restrict__ norms_out,
                   int N)
{
    const int w = threadIdx.x >> 5;      // warp 0..5
    const int l = threadIdx.x & 31;
    const int p0 = 128 * w + 4 * l;
    const int m  = p0 % 3;
    const int gA = p0 / 3;
    const int f4 = 32 * w + l;
    const int HALF = N >> 1;             // 4096

    float MA[9], MB[9];
    build_mat(rotors + (size_t)gA * 8, MA);
    build_mat(rotors + (size_t)(gA + 1) * 8, MB);

    const bool needPrev = (l == 0)  && ((128 * w) % 3 != 0);
    const bool needNext = (l == 31) && ((128 * (w + 1)) % 3 != 0);
    const float step = 2.0f / 15.0f;

    __shared__ __align__(16) float spart[2][2][8];   // [buf][stream][warp]

    // prologue loads for both streams' first rows
    int r1 = blockIdx.x;                 // stream 0: rows [0, HALF)
    float4 aA = make_float4(0, 0, 0, 0), aB = make_float4(0, 0, 0, 0);
    float2 pvA = make_float2(0, 0), nxA = make_float2(0, 0);
    float2 pvB = make_float2(0, 0), nxB = make_float2(0, 0);
    if (r1 < HALF) {
        const float* xr = x + (size_t)r1 * D;
        aA = __ldg(reinterpret_cast<const float4*>(xr) + f4);
        if (needPrev) pvA = __ldg(reinterpret_cast<const float2*>(xr + 128 * w - 2));
        if (needNext) nxA = __ldg(reinterpret_cast<const float2*>(xr + 128 * (w + 1)));
        const float* xs = xr + (size_t)HALF * D;
        aB = __ldg(reinterpret_cast<const float4*>(xs) + f4);
        if (needPrev) pvB = __ldg(reinterpret_cast<const float2*>(xs + 128 * w - 2));
        if (needNext) nxB = __ldg(reinterpret_cast<const float2*>(xs + 128 * (w + 1)));
    }

    int buf = 0;
    for (; r1 < HALF; r1 += NBLK) {
        const int r2 = r1 + HALF;

        // norm partials for both streams, one barrier
        float s1 = fmaf(aA.x, aA.x, fmaf(aA.y, aA.y, fmaf(aA.z, aA.z, aA.w * aA.w)));
        float s2 = fmaf(aB.x, aB.x, fmaf(aB.y, aB.y, fmaf(aB.z, aB.z, aB.w * aB.w)));
        #pragma unroll
        for (int o = 16; o; o >>= 1) {
            s1 += __shfl_xor_sync(0xffffffffu, s1, o);
            s2 += __shfl_xor_sync(0xffffffffu, s2, o);
        }
        if (l == 0) { spart[buf][0][w] = s1; spart[buf][1][w] = s2; }

        // prefetch next rows before the barrier
        const int n1 = r1 + NBLK;
        float4 aA2 = make_float4(0, 0, 0, 0), aB2 = make_float4(0, 0, 0, 0);
        float2 pvA2 = make_float2(0, 0), nxA2 = make_float2(0, 0);
        float2 pvB2 = make_float2(0, 0), nxB2 = make_float2(0, 0);
        if (n1 < HALF) {
            const float* xr = x + (size_t)n1 * D;
            aA2 = __ldg(reinterpret_cast<const float4*>(xr) + f4);
            if (needPrev) pvA2 = __ldg(reinterpret_cast<const float2*>(xr + 128 * w - 2));
            if (needNext) nxA2 = __ldg(reinterpret_cast<const float2*>(xr + 128 * (w + 1)));
            const float* xs = xr + (size_t)HALF * D;
            aB2 = __ldg(reinterpret_cast<const float4*>(xs) + f4);
            if (needPrev) pvB2 = __ldg(reinterpret_cast<const float2*>(xs + 128 * w - 2));
            if (needNext) nxB2 = __ldg(reinterpret_cast<const float2*>(xs + 128 * (w + 1)));
        }

        __syncthreads();
        float4 u4 = *reinterpret_cast<float4*>(spart[buf][0]);
        float2 u2 = *reinterpret_cast<float2*>(spart[buf][0] + 4);
        float4 v4 = *reinterpret_cast<float4*>(spart[buf][1]);
        float2 v2 = *reinterpret_cast<float2*>(spart[buf][1] + 4);
        buf ^= 1;
        const float nrm1 = fmaxf(sqrtf(u4.x + u4.y + u4.z + u4.w + u2.x + u2.y), 1e-8f);
        const float nrm2 = fmaxf(sqrtf(v4.x + v4.y + v4.z + v4.w + v2.x + v2.y), 1e-8f);
        const float inv1 = 1.0f / nrm1, inv2 = 1.0f / nrm2;
        const float qs1 = step * nrm1, qb1 = -nrm1;
        const float qs2 = step * nrm2, qb2 = -nrm2;

        float4 oh1, oi1, oh2, oi2;
        body(MA, MB, m, l, aA, pvA, nxA, inv1, qs1, qb1, oh1, oi1);
        body(MA, MB, m, l, aB, pvB, nxB, inv2, qs2, qb2, oh2, oi2);

        reinterpret_cast<float4*>(xhat + (size_t)r1 * D)[f4] = oh1;
        reinterpret_cast<float4*>(xhat + (size_t)r2 * D)[f4] = oh2;
        if (idx_out) {
            reinterpret_cast<float4*>(idx_out + (size_t)r1 * D)[f4] = oi1;
            reinterpret_cast<float4*>(idx_out + (size_t)r2 * D)[f4] = oi2;
        }
        if (threadIdx.x == 0 && norms_out) {
            norms_out[r1] = nrm1;
            norms_out[r2] = nrm2;
        }

        aA = aA2; pvA = pvA2; nxA = nxA2;
        aB = aB2; pvB = pvB2; nxB = nxB2;
    }
}

extern "C" void kernel_launch(void* const* d_in, const int* in_sizes, int n_in,
                              void* d_out, int out_size)
{
    const float* x      = (const float*)d_in[0];   // [N, d]
    const float* rotors = (const float*)d_in[2];   // [G, 8]

    const int G = in_sizes[2] / 8;        // 256
    const int d = 3 * G;                  // 768
    const int N = in_sizes[0] / d;        // 8192

    float* out   = (float*)d_out;
    float* xhat  = out;
    float* idxp  = nullptr;
    float* normp = nullptr;
    const long nd = (long)N * d;
    if ((long)out_size >= 2 * nd)     idxp  = out + nd;
    if ((long)out_size >= 2 * nd + N) normp = out + 2 * nd;

    rotor_quant_kernel<<<NBLK, 192>>>(x, rotors, xhat, idxp, normp, N);
}